// round 14
// baseline (speedup 1.0000x reference)
#include <cuda_runtime.h>

#define NM 1024
#define HH 256
#define WW 256
#define HWsz 65536
#define MCAP 256

// Scratch (allocation-free: __device__ globals; zero-init at load)
__device__ float g_boxes[NM * 4];
__device__ int   g_valid[NM];
__device__ float g_gated[NM];
__device__ int   g_flag;

// ---------------------------------------------------------------------------
// Kernel A: per-mask stats. Proven shape (31 regs, ~45us read-only).
// Block 0 also resets the NMS-done flag for the following kernel.
// ---------------------------------------------------------------------------
__global__ __launch_bounds__(256) void stats_kernel(const float* __restrict__ logits,
                                                    const float* __restrict__ iou) {
    if (blockIdx.x == 0 && threadIdx.x == 0) g_flag = 0;   // ordered by kernel boundary
    int n = blockIdx.x;
    const float4* p = (const float4*)(logits + (size_t)n * HWsz);

    int hi = 0, lo = 0;
    int minX = WW, maxX = -1, minY = HH, maxY = -1;

    for (int k = threadIdx.x; k < HWsz / 8; k += 256) {
        float4 a = p[k];
        float4 b = p[k + HWsz / 8];
        {
            int lin = k << 2;
            int y = lin >> 8, x = lin & 255;
            hi += (a.x > 1.0f) + (a.y > 1.0f) + (a.z > 1.0f) + (a.w > 1.0f);
            lo += (a.x > -1.0f) + (a.y > -1.0f) + (a.z > -1.0f) + (a.w > -1.0f);
            unsigned m = (a.x > 0.0f ? 1u : 0u) | (a.y > 0.0f ? 2u : 0u) |
                         (a.z > 0.0f ? 4u : 0u) | (a.w > 0.0f ? 8u : 0u);
            if (m) {
                minY = min(minY, y); maxY = max(maxY, y);
                minX = min(minX, x + (__ffs(m) - 1));
                maxX = max(maxX, x + (31 - __clz(m)));
            }
        }
        {
            int lin = (k + HWsz / 8) << 2;
            int y = lin >> 8, x = lin & 255;
            hi += (b.x > 1.0f) + (b.y > 1.0f) + (b.z > 1.0f) + (b.w > 1.0f);
            lo += (b.x > -1.0f) + (b.y > -1.0f) + (b.z > -1.0f) + (b.w > -1.0f);
            unsigned m = (b.x > 0.0f ? 1u : 0u) | (b.y > 0.0f ? 2u : 0u) |
                         (b.z > 0.0f ? 4u : 0u) | (b.w > 0.0f ? 8u : 0u);
            if (m) {
                minY = min(minY, y); maxY = max(maxY, y);
                minX = min(minX, x + (__ffs(m) - 1));
                maxX = max(maxX, x + (31 - __clz(m)));
            }
        }
    }

    #pragma unroll
    for (int off = 16; off; off >>= 1) {
        hi += __shfl_down_sync(0xFFFFFFFFu, hi, off);
        lo += __shfl_down_sync(0xFFFFFFFFu, lo, off);
        minX = min(minX, __shfl_down_sync(0xFFFFFFFFu, minX, off));
        maxX = max(maxX, __shfl_down_sync(0xFFFFFFFFu, maxX, off));
        minY = min(minY, __shfl_down_sync(0xFFFFFFFFu, minY, off));
        maxY = max(maxY, __shfl_down_sync(0xFFFFFFFFu, maxY, off));
    }

    __shared__ int s[6][8];
    int wid = threadIdx.x >> 5, lane = threadIdx.x & 31;
    if (lane == 0) {
        s[0][wid] = hi; s[1][wid] = lo;
        s[2][wid] = minX; s[3][wid] = maxX;
        s[4][wid] = minY; s[5][wid] = maxY;
    }
    __syncthreads();
    if (threadIdx.x == 0) {
        int Hc = 0, Lc = 0, mX = WW, MX = -1, mY = HH, MY = -1;
        #pragma unroll
        for (int w = 0; w < 8; w++) {
            Hc += s[0][w]; Lc += s[1][w];
            mX = min(mX, s[2][w]); MX = max(MX, s[3][w]);
            mY = min(mY, s[4][w]); MY = max(MY, s[5][w]);
        }
        float stab = (float)Hc / fmaxf((float)Lc, 1.0f);
        float sc = iou[n];
        g_valid[n] = (sc > 0.88f) && (stab >= 0.95f);
        float x0, y0, x1, y1;
        if (MY < 0) { x0 = y0 = x1 = y1 = 0.0f; }
        else { x0 = (float)mX; y0 = (float)mY; x1 = (float)MX; y1 = (float)MY; }
        g_boxes[n * 4 + 0] = x0;
        g_boxes[n * 4 + 1] = y0;
        g_boxes[n * 4 + 2] = x1;
        g_boxes[n * 4 + 3] = y1;
    }
}

// ---------------------------------------------------------------------------
// Kernel B: everything else, one launch. Grid = 1 + NM + 16*NM blocks.
//   block 0                : bitmatrix NMS -> g_gated, tail outputs, set flag
//   blocks 1..NM           : stcs zero-fill for INVALID masks (no dependency)
//   blocks NM+1 ..         : valid-mask output; spin on flag (producer is
//                            block 0, resident from wave 1 -> no deadlock)
// ---------------------------------------------------------------------------
__global__ __launch_bounds__(256) void fused_kernel(const float* __restrict__ logits,
                                                    const float* __restrict__ iou,
                                                    float* __restrict__ out,
                                                    int write_tail) {
    int t = threadIdx.x;
    int bid = blockIdx.x;

    if (bid >= 1 && bid <= NM) {
        // ---- streaming zero-fill for one invalid mask ----
        int n = bid - 1;
        if (g_valid[n]) return;          // valid masks handled below
        float4* o = (float4*)(out + (size_t)n * HWsz);
        const float4 z = make_float4(0.0f, 0.0f, 0.0f, 0.0f);
        #pragma unroll 4
        for (int j = 0; j < 64; j++)
            __stcs(&o[j * 256 + t], z);
        return;
    }

    if (bid > NM) {
        // ---- valid-mask output: 16 blocks per mask ----
        int e = bid - NM - 1;
        int n = e >> 4;
        int chunk = e & 15;
        if (!g_valid[n]) return;         // no spin needed for invalid
        // wait for NMS result (block 0 is resident from wave 1)
        if (t == 0) {
            while (atomicAdd(&g_flag, 0) == 0) __nanosleep(200);
        }
        __syncthreads();
        __threadfence();
        float g = g_gated[n];
        size_t base = (size_t)n * HWsz;
        int i0 = chunk * 1024 + t;
        float4* o = (float4*)(out + base);
        if (g == 0.0f) {
            float4 z = make_float4(0.0f, 0.0f, 0.0f, 0.0f);
            #pragma unroll
            for (int j = 0; j < 4; j++) __stcs(&o[i0 + j * 256], z);
            return;
        }
        const float4* p = (const float4*)(logits + base);
        float4 v[4];
        #pragma unroll
        for (int j = 0; j < 4; j++) v[j] = __ldcs(&p[i0 + j * 256]);
        #pragma unroll
        for (int j = 0; j < 4; j++) {
            v[j].x = g / (1.0f + __expf(-v[j].x));
            v[j].y = g / (1.0f + __expf(-v[j].y));
            v[j].z = g / (1.0f + __expf(-v[j].z));
            v[j].w = g / (1.0f + __expf(-v[j].w));
            __stcs(&o[i0 + j * 256], v[j]);
        }
        return;
    }

    // =========================== block 0: NMS ==============================
    __shared__ short  sIdxV[MCAP];
    __shared__ float  sScoreV[MCAP];
    __shared__ short  sOrder[NM];
    __shared__ float4 sBoxS[MCAP];
    __shared__ unsigned sMat[MCAP][MCAP / 32];
    __shared__ short sKeepList[MCAP];
    __shared__ unsigned char sKO[NM];
    __shared__ int sM, sCnt;

    if (t == 0) { sM = 0; sCnt = 0; }
    for (int i = t; i < NM; i += 256) sKO[i] = 0;
    __syncthreads();

    for (int i = t; i < NM; i += 256) {
        if (g_valid[i]) {
            int pos = atomicAdd(&sM, 1);
            if (pos < MCAP) { sIdxV[pos] = (short)i; sScoreV[pos] = iou[i]; }
        }
    }
    __syncthreads();
    int M = sM;

    if (M <= MCAP) {
        if (t < M) {
            int i = sIdxV[t];
            float ki = sScoreV[t];
            int rank = 0;
            for (int u = 0; u < M; u++) {
                int j = sIdxV[u];
                float kj = sScoreV[u];
                rank += (kj > ki) || (kj == ki && j < i);
            }
            sOrder[rank] = (short)i;
        }
        __syncthreads();
        if (t < M) {
            int orig = sOrder[t];
            sBoxS[t] = make_float4(g_boxes[orig * 4 + 0], g_boxes[orig * 4 + 1],
                                   g_boxes[orig * 4 + 2], g_boxes[orig * 4 + 3]);
        }
        __syncthreads();

        int nw = (M + 31) >> 5;
        for (int e = t; e < M * nw; e += 256) {
            int i = e / nw, w = e % nw;
            float4 bi = sBoxS[i];
            float areaA = fmaxf(bi.z - bi.x, 0.0f) * fmaxf(bi.w - bi.y, 0.0f);
            unsigned bits = 0;
            int jbase = w << 5;
            #pragma unroll 8
            for (int b = 0; b < 32; b++) {
                int j = jbase + b;
                if (j < M && j > i) {
                    float4 bj = sBoxS[j];
                    float x0 = fmaxf(bi.x, bj.x), y0 = fmaxf(bi.y, bj.y);
                    float x1 = fminf(bi.z, bj.z), y1 = fminf(bi.w, bj.w);
                    float inter = fmaxf(x1 - x0, 0.0f) * fmaxf(y1 - y0, 0.0f);
                    float areaB = fmaxf(bj.z - bj.x, 0.0f) * fmaxf(bj.w - bj.y, 0.0f);
                    float v = inter / fmaxf(areaA + areaB - inter, 1e-6f);
                    if (v > 0.7f) bits |= (1u << b);
                }
            }
            sMat[i][w] = bits;
        }
        __syncthreads();

        if (t == 0) {
            unsigned alive[MCAP / 32];
            #pragma unroll
            for (int w = 0; w < MCAP / 32; w++) {
                int lo32 = w << 5;
                if (M >= lo32 + 32) alive[w] = 0xFFFFFFFFu;
                else if (M <= lo32) alive[w] = 0u;
                else alive[w] = (1u << (M - lo32)) - 1u;
            }
            int cnt = 0;
            int nwv = (M + 31) >> 5;
            for (int i = 0; i < M; i++) {
                if (!((alive[i >> 5] >> (i & 31)) & 1u)) continue;
                sKeepList[cnt++] = (short)i;
                for (int w = 0; w < nwv; w++) alive[w] &= ~sMat[i][w];
            }
            sCnt = cnt;
        }
        __syncthreads();
        for (int r = t; r < sCnt; r += 256)
            sKO[sOrder[sKeepList[r]]] = 1;
        __syncthreads();
    } else {
        // Fallback (M > 256, practically unreachable): warp-0 greedy over all.
        for (int s0 = t; s0 < M; s0 += 256) {
            int seen = -1, i = -1;
            for (int q = 0; q < NM; q++) { if (g_valid[q]) { if (++seen == s0) { i = q; break; } } }
            float ki = iou[i];
            int rank = 0;
            for (int u = 0; u < NM; u++) {
                if (!g_valid[u]) continue;
                float kj = iou[u];
                rank += (kj > ki) || (kj == ki && u < i);
            }
            sOrder[rank] = (short)i;
        }
        __syncthreads();
        if (t < 32) {
            int lane2 = t;
            unsigned al = 0;
            #pragma unroll
            for (int b = 0; b < 32; b++)
                if (b * 32 + lane2 < M) al |= (1u << b);
            unsigned keepbits = 0;
            while (true) {
                int cand = al ? ((__ffs(al) - 1) * 32 + lane2) : 0x7FFFFFFF;
                #pragma unroll
                for (int off = 16; off; off >>= 1)
                    cand = min(cand, __shfl_xor_sync(0xFFFFFFFFu, cand, off));
                if (cand == 0x7FFFFFFF) break;
                int i = cand;
                if ((i & 31) == lane2) {
                    keepbits |= (1u << (i >> 5));
                    al &= ~(1u << (i >> 5));
                }
                int oi = sOrder[i];
                float4 bi = make_float4(g_boxes[oi * 4 + 0], g_boxes[oi * 4 + 1],
                                        g_boxes[oi * 4 + 2], g_boxes[oi * 4 + 3]);
                float areaA = fmaxf(bi.z - bi.x, 0.0f) * fmaxf(bi.w - bi.y, 0.0f);
                unsigned m = al;
                while (m) {
                    int b = __ffs(m) - 1; m &= m - 1;
                    int oj = sOrder[b * 32 + lane2];
                    float4 bj = make_float4(g_boxes[oj * 4 + 0], g_boxes[oj * 4 + 1],
                                            g_boxes[oj * 4 + 2], g_boxes[oj * 4 + 3]);
                    float x0 = fmaxf(bi.x, bj.x), y0 = fmaxf(bi.y, bj.y);
                    float x1 = fminf(bi.z, bj.z), y1 = fminf(bi.w, bj.w);
                    float inter = fmaxf(x1 - x0, 0.0f) * fmaxf(y1 - y0, 0.0f);
                    float areaB = fmaxf(bj.z - bj.x, 0.0f) * fmaxf(bj.w - bj.y, 0.0f);
                    float v = inter / fmaxf(areaA + areaB - inter, 1e-6f);
                    if (v > 0.7f) al &= ~(1u << b);
                }
            }
            while (keepbits) {
                int b = __ffs(keepbits) - 1; keepbits &= keepbits - 1;
                sKO[sOrder[b * 32 + lane2]] = 1;
            }
        }
        __syncthreads();
    }

    // publish gated values + tail outputs, then release spinners
    size_t base = (size_t)NM * HWsz;
    for (int i = t; i < NM; i += 256) {
        float k = sKO[i] ? 1.0f : 0.0f;
        g_gated[i] = k * iou[i];
        if (write_tail) {
            out[base + i] = k;
            out[base + NM + (size_t)i * 4 + 0] = g_boxes[i * 4 + 0];
            out[base + NM + (size_t)i * 4 + 1] = g_boxes[i * 4 + 1];
            out[base + NM + (size_t)i * 4 + 2] = g_boxes[i * 4 + 2];
            out[base + NM + (size_t)i * 4 + 3] = g_boxes[i * 4 + 3];
        }
    }
    __syncthreads();
    if (t == 0) {
        __threadfence();
        atomicExch(&g_flag, 1);
    }
}

extern "C" void kernel_launch(void* const* d_in, const int* in_sizes, int n_in,
                              void* d_out, int out_size) {
    const float* logits = (const float*)d_in[0];  // [1024,256,256]
    const float* iou    = (const float*)d_in[1];  // [1024]
    float* out = (float*)d_out;

    int write_tail = (out_size >= NM * HWsz + NM + NM * 4) ? 1 : 0;

    stats_kernel<<<NM, 256>>>(logits, iou);
    fused_kernel<<<1 + NM + 16 * NM, 256>>>(logits, iou, out, write_tail);
}

// round 16
// speedup vs baseline: 1.1010x; 1.1010x over previous
#include <cuda_runtime.h>

#define NM 1024
#define HH 256
#define WW 256
#define HWsz 65536
#define MCAP 256

// Scratch (allocation-free: __device__ globals; zero-init at load)
__device__ float g_boxes[NM * 4];
__device__ int   g_valid[NM];
__device__ float g_gated[NM];
__device__ int   g_flag;

// ---------------------------------------------------------------------------
// Kernel A: per-mask stats. Proven shape (31 regs, ~45us read-only).
// Block 0 also resets the NMS-done flag (ordered by kernel boundary).
// ---------------------------------------------------------------------------
__global__ __launch_bounds__(256) void stats_kernel(const float* __restrict__ logits,
                                                    const float* __restrict__ iou) {
    if (blockIdx.x == 0 && threadIdx.x == 0) g_flag = 0;
    int n = blockIdx.x;
    const float4* p = (const float4*)(logits + (size_t)n * HWsz);

    int hi = 0, lo = 0;
    int minX = WW, maxX = -1, minY = HH, maxY = -1;

    for (int k = threadIdx.x; k < HWsz / 8; k += 256) {
        float4 a = p[k];
        float4 b = p[k + HWsz / 8];
        {
            int lin = k << 2;
            int y = lin >> 8, x = lin & 255;
            hi += (a.x > 1.0f) + (a.y > 1.0f) + (a.z > 1.0f) + (a.w > 1.0f);
            lo += (a.x > -1.0f) + (a.y > -1.0f) + (a.z > -1.0f) + (a.w > -1.0f);
            unsigned m = (a.x > 0.0f ? 1u : 0u) | (a.y > 0.0f ? 2u : 0u) |
                         (a.z > 0.0f ? 4u : 0u) | (a.w > 0.0f ? 8u : 0u);
            if (m) {
                minY = min(minY, y); maxY = max(maxY, y);
                minX = min(minX, x + (__ffs(m) - 1));
                maxX = max(maxX, x + (31 - __clz(m)));
            }
        }
        {
            int lin = (k + HWsz / 8) << 2;
            int y = lin >> 8, x = lin & 255;
            hi += (b.x > 1.0f) + (b.y > 1.0f) + (b.z > 1.0f) + (b.w > 1.0f);
            lo += (b.x > -1.0f) + (b.y > -1.0f) + (b.z > -1.0f) + (b.w > -1.0f);
            unsigned m = (b.x > 0.0f ? 1u : 0u) | (b.y > 0.0f ? 2u : 0u) |
                         (b.z > 0.0f ? 4u : 0u) | (b.w > 0.0f ? 8u : 0u);
            if (m) {
                minY = min(minY, y); maxY = max(maxY, y);
                minX = min(minX, x + (__ffs(m) - 1));
                maxX = max(maxX, x + (31 - __clz(m)));
            }
        }
    }

    #pragma unroll
    for (int off = 16; off; off >>= 1) {
        hi += __shfl_down_sync(0xFFFFFFFFu, hi, off);
        lo += __shfl_down_sync(0xFFFFFFFFu, lo, off);
        minX = min(minX, __shfl_down_sync(0xFFFFFFFFu, minX, off));
        maxX = max(maxX, __shfl_down_sync(0xFFFFFFFFu, maxX, off));
        minY = min(minY, __shfl_down_sync(0xFFFFFFFFu, minY, off));
        maxY = max(maxY, __shfl_down_sync(0xFFFFFFFFu, maxY, off));
    }

    __shared__ int s[6][8];
    int wid = threadIdx.x >> 5, lane = threadIdx.x & 31;
    if (lane == 0) {
        s[0][wid] = hi; s[1][wid] = lo;
        s[2][wid] = minX; s[3][wid] = maxX;
        s[4][wid] = minY; s[5][wid] = maxY;
    }
    __syncthreads();
    if (threadIdx.x == 0) {
        int Hc = 0, Lc = 0, mX = WW, MX = -1, mY = HH, MY = -1;
        #pragma unroll
        for (int w = 0; w < 8; w++) {
            Hc += s[0][w]; Lc += s[1][w];
            mX = min(mX, s[2][w]); MX = max(MX, s[3][w]);
            mY = min(mY, s[4][w]); MY = max(MY, s[5][w]);
        }
        float stab = (float)Hc / fmaxf((float)Lc, 1.0f);
        float sc = iou[n];
        g_valid[n] = (sc > 0.88f) && (stab >= 0.95f);
        float x0, y0, x1, y1;
        if (MY < 0) { x0 = y0 = x1 = y1 = 0.0f; }
        else { x0 = (float)mX; y0 = (float)mY; x1 = (float)MX; y1 = (float)MY; }
        g_boxes[n * 4 + 0] = x0;
        g_boxes[n * 4 + 1] = y0;
        g_boxes[n * 4 + 2] = x1;
        g_boxes[n * 4 + 3] = y1;
    }
}

// ---------------------------------------------------------------------------
// Kernel B: grid = 1 + 16*NM.
//   block 0        : bitmatrix NMS -> g_gated, tail outputs, set flag
//   blocks 1..     : one 16KB chunk of one mask (R10-proven geometry):
//                    invalid mask -> stcs zeros immediately (no dependency)
//                    valid mask   -> spin on flag, then sigmoid*g or zeros
// ---------------------------------------------------------------------------
__global__ __launch_bounds__(256) void fused_kernel(const float* __restrict__ logits,
                                                    const float* __restrict__ iou,
                                                    float* __restrict__ out,
                                                    int write_tail) {
    int t = threadIdx.x;
    int bid = blockIdx.x;

    if (bid > 0) {
        int e = bid - 1;
        int n = e >> 4;
        int chunk = e & 15;
        size_t base = (size_t)n * HWsz;
        int i0 = chunk * 1024 + t;
        float4* o = (float4*)(out + base);

        if (!g_valid[n]) {
            float4 z = make_float4(0.0f, 0.0f, 0.0f, 0.0f);
            #pragma unroll
            for (int j = 0; j < 4; j++) __stcs(&o[i0 + j * 256], z);
            return;
        }
        // valid: wait for NMS result (block 0 resident from wave 1)
        if (t == 0) {
            while (atomicAdd(&g_flag, 0) == 0) __nanosleep(200);
        }
        __syncthreads();
        __threadfence();
        float g = g_gated[n];
        if (g == 0.0f) {
            float4 z = make_float4(0.0f, 0.0f, 0.0f, 0.0f);
            #pragma unroll
            for (int j = 0; j < 4; j++) __stcs(&o[i0 + j * 256], z);
            return;
        }
        const float4* p = (const float4*)(logits + base);
        float4 v[4];
        #pragma unroll
        for (int j = 0; j < 4; j++) v[j] = __ldcs(&p[i0 + j * 256]);
        #pragma unroll
        for (int j = 0; j < 4; j++) {
            v[j].x = g / (1.0f + __expf(-v[j].x));
            v[j].y = g / (1.0f + __expf(-v[j].y));
            v[j].z = g / (1.0f + __expf(-v[j].z));
            v[j].w = g / (1.0f + __expf(-v[j].w));
            __stcs(&o[i0 + j * 256], v[j]);
        }
        return;
    }

    // =========================== block 0: NMS ==============================
    __shared__ short  sIdxV[MCAP];
    __shared__ float  sScoreV[MCAP];
    __shared__ short  sOrder[NM];
    __shared__ float4 sBoxS[MCAP];
    __shared__ unsigned sMat[MCAP][MCAP / 32];
    __shared__ short sKeepList[MCAP];
    __shared__ unsigned char sKO[NM];
    __shared__ int sM, sCnt;

    if (t == 0) { sM = 0; sCnt = 0; }
    for (int i = t; i < NM; i += 256) sKO[i] = 0;
    __syncthreads();

    for (int i = t; i < NM; i += 256) {
        if (g_valid[i]) {
            int pos = atomicAdd(&sM, 1);
            if (pos < MCAP) { sIdxV[pos] = (short)i; sScoreV[pos] = iou[i]; }
        }
    }
    __syncthreads();
    int M = sM;

    if (M <= MCAP) {
        if (t < M) {
            int i = sIdxV[t];
            float ki = sScoreV[t];
            int rank = 0;
            for (int u = 0; u < M; u++) {
                int j = sIdxV[u];
                float kj = sScoreV[u];
                rank += (kj > ki) || (kj == ki && j < i);
            }
            sOrder[rank] = (short)i;
        }
        __syncthreads();
        if (t < M) {
            int orig = sOrder[t];
            sBoxS[t] = make_float4(g_boxes[orig * 4 + 0], g_boxes[orig * 4 + 1],
                                   g_boxes[orig * 4 + 2], g_boxes[orig * 4 + 3]);
        }
        __syncthreads();

        int nw = (M + 31) >> 5;
        for (int e = t; e < M * nw; e += 256) {
            int i = e / nw, w = e % nw;
            float4 bi = sBoxS[i];
            float areaA = fmaxf(bi.z - bi.x, 0.0f) * fmaxf(bi.w - bi.y, 0.0f);
            unsigned bits = 0;
            int jbase = w << 5;
            #pragma unroll 8
            for (int b = 0; b < 32; b++) {
                int j = jbase + b;
                if (j < M && j > i) {
                    float4 bj = sBoxS[j];
                    float x0 = fmaxf(bi.x, bj.x), y0 = fmaxf(bi.y, bj.y);
                    float x1 = fminf(bi.z, bj.z), y1 = fminf(bi.w, bj.w);
                    float inter = fmaxf(x1 - x0, 0.0f) * fmaxf(y1 - y0, 0.0f);
                    float areaB = fmaxf(bj.z - bj.x, 0.0f) * fmaxf(bj.w - bj.y, 0.0f);
                    float v = inter / fmaxf(areaA + areaB - inter, 1e-6f);
                    if (v > 0.7f) bits |= (1u << b);
                }
            }
            sMat[i][w] = bits;
        }
        __syncthreads();

        if (t == 0) {
            unsigned alive[MCAP / 32];
            #pragma unroll
            for (int w = 0; w < MCAP / 32; w++) {
                int lo32 = w << 5;
                if (M >= lo32 + 32) alive[w] = 0xFFFFFFFFu;
                else if (M <= lo32) alive[w] = 0u;
                else alive[w] = (1u << (M - lo32)) - 1u;
            }
            int cnt = 0;
            int nwv = (M + 31) >> 5;
            for (int i = 0; i < M; i++) {
                if (!((alive[i >> 5] >> (i & 31)) & 1u)) continue;
                sKeepList[cnt++] = (short)i;
                for (int w = 0; w < nwv; w++) alive[w] &= ~sMat[i][w];
            }
            sCnt = cnt;
        }
        __syncthreads();
        for (int r = t; r < sCnt; r += 256)
            sKO[sOrder[sKeepList[r]]] = 1;
        __syncthreads();
    } else {
        // Fallback (M > 256, practically unreachable): warp-0 greedy over all.
        for (int s0 = t; s0 < M; s0 += 256) {
            int seen = -1, i = -1;
            for (int q = 0; q < NM; q++) { if (g_valid[q]) { if (++seen == s0) { i = q; break; } } }
            float ki = iou[i];
            int rank = 0;
            for (int u = 0; u < NM; u++) {
                if (!g_valid[u]) continue;
                float kj = iou[u];
                rank += (kj > ki) || (kj == ki && u < i);
            }
            sOrder[rank] = (short)i;
        }
        __syncthreads();
        if (t < 32) {
            int lane2 = t;
            unsigned al = 0;
            #pragma unroll
            for (int b = 0; b < 32; b++)
                if (b * 32 + lane2 < M) al |= (1u << b);
            unsigned keepbits = 0;
            while (true) {
                int cand = al ? ((__ffs(al) - 1) * 32 + lane2) : 0x7FFFFFFF;
                #pragma unroll
                for (int off = 16; off; off >>= 1)
                    cand = min(cand, __shfl_xor_sync(0xFFFFFFFFu, cand, off));
                if (cand == 0x7FFFFFFF) break;
                int i = cand;
                if ((i & 31) == lane2) {
                    keepbits |= (1u << (i >> 5));
                    al &= ~(1u << (i >> 5));
                }
                int oi = sOrder[i];
                float4 bi = make_float4(g_boxes[oi * 4 + 0], g_boxes[oi * 4 + 1],
                                        g_boxes[oi * 4 + 2], g_boxes[oi * 4 + 3]);
                float areaA = fmaxf(bi.z - bi.x, 0.0f) * fmaxf(bi.w - bi.y, 0.0f);
                unsigned m = al;
                while (m) {
                    int b = __ffs(m) - 1; m &= m - 1;
                    int oj = sOrder[b * 32 + lane2];
                    float4 bj = make_float4(g_boxes[oj * 4 + 0], g_boxes[oj * 4 + 1],
                                            g_boxes[oj * 4 + 2], g_boxes[oj * 4 + 3]);
                    float x0 = fmaxf(bi.x, bj.x), y0 = fmaxf(bi.y, bj.y);
                    float x1 = fminf(bi.z, bj.z), y1 = fminf(bi.w, bj.w);
                    float inter = fmaxf(x1 - x0, 0.0f) * fmaxf(y1 - y0, 0.0f);
                    float areaB = fmaxf(bj.z - bj.x, 0.0f) * fmaxf(bj.w - bj.y, 0.0f);
                    float v = inter / fmaxf(areaA + areaB - inter, 1e-6f);
                    if (v > 0.7f) al &= ~(1u << b);
                }
            }
            while (keepbits) {
                int b = __ffs(keepbits) - 1; keepbits &= keepbits - 1;
                sKO[sOrder[b * 32 + lane2]] = 1;
            }
        }
        __syncthreads();
    }

    // publish gated values + tail outputs, then release spinners
    size_t base = (size_t)NM * HWsz;
    for (int i = t; i < NM; i += 256) {
        float k = sKO[i] ? 1.0f : 0.0f;
        g_gated[i] = k * iou[i];
        if (write_tail) {
            out[base + i] = k;
            out[base + NM + (size_t)i * 4 + 0] = g_boxes[i * 4 + 0];
            out[base + NM + (size_t)i * 4 + 1] = g_boxes[i * 4 + 1];
            out[base + NM + (size_t)i * 4 + 2] = g_boxes[i * 4 + 2];
            out[base + NM + (size_t)i * 4 + 3] = g_boxes[i * 4 + 3];
        }
    }
    __syncthreads();
    if (t == 0) {
        __threadfence();
        atomicExch(&g_flag, 1);
    }
}

extern "C" void kernel_launch(void* const* d_in, const int* in_sizes, int n_in,
                              void* d_out, int out_size) {
    const float* logits = (const float*)d_in[0];  // [1024,256,256]
    const float* iou    = (const float*)d_in[1];  // [1024]
    float* out = (float*)d_out;

    int write_tail = (out_size >= NM * HWsz + NM + NM * 4) ? 1 : 0;

    stats_kernel<<<NM, 256>>>(logits, iou);
    fused_kernel<<<1 + 16 * NM, 256>>>(logits, iou, out, write_tail);
}